// round 1
// baseline (speedup 1.0000x reference)
#include <cuda_runtime.h>
#include <math.h>

#define DM   1024
#define NH   16
#define HD   64
#define SEQ  2048
#define BATCH 2
#define MROWS (BATCH*SEQ)   // 4096

// Scratch (static device arrays — no allocation allowed)
__device__ float g_q[MROWS*DM];
__device__ float g_k[MROWS*DM];
__device__ float g_v[MROWS*DM];
__device__ float g_ctx[MROWS*DM];

// ---------------------------------------------------------------------------
// SGEMM (NT): C[M,N] = A[M,K] @ B[N,K]^T (+ bias). M,N mult of 128, K mult of 16.
// ---------------------------------------------------------------------------
template<bool HAS_BIAS>
__global__ void __launch_bounds__(256, 2) gemm_nt_kernel(
    const float* __restrict__ A, const float* __restrict__ B,
    const float* __restrict__ bias, float* __restrict__ C,
    int M, int N, int K)
{
    __shared__ float As[16][132];
    __shared__ float Bs[16][132];
    const int bm = blockIdx.y * 128;
    const int bn = blockIdx.x * 128;
    const int tid = threadIdx.x;
    const int tx = tid & 15, ty = tid >> 4;

    float acc[8][8];
    #pragma unroll
    for (int i = 0; i < 8; i++)
        #pragma unroll
        for (int j = 0; j < 8; j++) acc[i][j] = 0.f;

    for (int k0 = 0; k0 < K; k0 += 16) {
        #pragma unroll
        for (int it = 0; it < 2; it++) {
            int idx = tid + it * 256;          // 0..511
            int m = idx >> 2, kq = idx & 3;
            const float4 va = *reinterpret_cast<const float4*>(
                &A[(size_t)(bm + m) * K + k0 + kq * 4]);
            As[kq*4+0][m] = va.x; As[kq*4+1][m] = va.y;
            As[kq*4+2][m] = va.z; As[kq*4+3][m] = va.w;
            const float4 vb = *reinterpret_cast<const float4*>(
                &B[(size_t)(bn + m) * K + k0 + kq * 4]);
            Bs[kq*4+0][m] = vb.x; Bs[kq*4+1][m] = vb.y;
            Bs[kq*4+2][m] = vb.z; Bs[kq*4+3][m] = vb.w;
        }
        __syncthreads();
        #pragma unroll
        for (int k = 0; k < 16; k++) {
            float a[8], b[8];
            *reinterpret_cast<float4*>(&a[0]) = *reinterpret_cast<float4*>(&As[k][ty*8]);
            *reinterpret_cast<float4*>(&a[4]) = *reinterpret_cast<float4*>(&As[k][ty*8+4]);
            *reinterpret_cast<float4*>(&b[0]) = *reinterpret_cast<float4*>(&Bs[k][tx*8]);
            *reinterpret_cast<float4*>(&b[4]) = *reinterpret_cast<float4*>(&Bs[k][tx*8+4]);
            #pragma unroll
            for (int i = 0; i < 8; i++)
                #pragma unroll
                for (int j = 0; j < 8; j++)
                    acc[i][j] += a[i] * b[j];
        }
        __syncthreads();
    }

    #pragma unroll
    for (int i = 0; i < 8; i++) {
        int row = bm + ty * 8 + i;
        #pragma unroll
        for (int j4 = 0; j4 < 2; j4++) {
            int col = bn + tx * 8 + j4 * 4;
            float4 o;
            o.x = acc[i][j4*4+0]; o.y = acc[i][j4*4+1];
            o.z = acc[i][j4*4+2]; o.w = acc[i][j4*4+3];
            if (HAS_BIAS) {
                o.x += bias[col+0]; o.y += bias[col+1];
                o.z += bias[col+2]; o.w += bias[col+3];
            }
            *reinterpret_cast<float4*>(&C[(size_t)row * N + col]) = o;
        }
    }
}

// ---------------------------------------------------------------------------
// RoPE: interleaved pairs within each head, applied in-place to q and k.
// ---------------------------------------------------------------------------
__global__ void rope_kernel(float* __restrict__ q, float* __restrict__ k, int npairs)
{
    int idx = blockIdx.x * blockDim.x + threadIdx.x;
    if (idx >= npairs) return;
    int row = idx >> 9;          // / (DM/2)
    int pc  = idx & 511;
    int h   = pc >> 5;           // 32 pairs per head
    int i   = pc & 31;
    int s   = row & (SEQ - 1);

    float theta = powf(10000.0f, -(float)(2 * i) * (1.0f / 64.0f));
    float ang = (float)s * theta;
    float sn, cs;
    sincosf(ang, &sn, &cs);

    size_t off = (size_t)row * DM + h * HD + 2 * i;
    float2 vq = *reinterpret_cast<float2*>(q + off);
    float2 rq;
    rq.x = vq.x * cs - vq.y * sn;
    rq.y = vq.y * cs + vq.x * sn;
    *reinterpret_cast<float2*>(q + off) = rq;

    float2 vk = *reinterpret_cast<float2*>(k + off);
    float2 rk;
    rk.x = vk.x * cs - vk.y * sn;
    rk.y = vk.y * cs + vk.x * sn;
    *reinterpret_cast<float2*>(k + off) = rk;
}

// ---------------------------------------------------------------------------
// Flash attention (causal): block = (query tile 64, head, batch).
// Threads 16x16; each thread owns a 4x4 score micro-tile and 4x4 of O.
// ---------------------------------------------------------------------------
__global__ void __launch_bounds__(256, 2) attn_kernel(
    const float* __restrict__ q, const float* __restrict__ k,
    const float* __restrict__ v, const int* __restrict__ mask,
    float* __restrict__ ctx)
{
    extern __shared__ float sm[];
    float (*Qs)[68] = reinterpret_cast<float(*)[68]>(sm);
    float (*Ks)[68] = reinterpret_cast<float(*)[68]>(sm + 64*68);
    float (*Vs)[68] = reinterpret_cast<float(*)[68]>(sm + 2*64*68);
    float (*Ps)[68] = reinterpret_cast<float(*)[68]>(sm + 3*64*68);
    int* msk = reinterpret_cast<int*>(sm + 4*64*68);

    const int qt = blockIdx.x, h = blockIdx.y, b = blockIdx.z;
    const int tid = threadIdx.x;
    const int tx = tid & 15, ty = tid >> 4;

    // Load Q tile (64 rows x 64 dims)
    #pragma unroll
    for (int it = 0; it < 4; it++) {
        int idx = tid + it * 256;          // 0..1023 float4s
        int r = idx >> 4, c4 = idx & 15;
        const float4 vq = *reinterpret_cast<const float4*>(
            &q[(size_t)(b * SEQ + qt * 64 + r) * DM + h * HD + c4 * 4]);
        *reinterpret_cast<float4*>(&Qs[r][c4 * 4]) = vq;
    }

    float o[4][4];
    #pragma unroll
    for (int i = 0; i < 4; i++)
        #pragma unroll
        for (int j = 0; j < 4; j++) o[i][j] = 0.f;
    float mrow[4], lrow[4];
    #pragma unroll
    for (int i = 0; i < 4; i++) { mrow[i] = -1e30f; lrow[i] = 0.f; }

    for (int kt = 0; kt <= qt; kt++) {
        __syncthreads();   // prior PV reads done before overwriting K/V
        #pragma unroll
        for (int it = 0; it < 4; it++) {
            int idx = tid + it * 256;
            int r = idx >> 4, c4 = idx & 15;
            size_t goff = (size_t)(b * SEQ + kt * 64 + r) * DM + h * HD + c4 * 4;
            *reinterpret_cast<float4*>(&Ks[r][c4 * 4]) =
                *reinterpret_cast<const float4*>(&k[goff]);
            *reinterpret_cast<float4*>(&Vs[r][c4 * 4]) =
                *reinterpret_cast<const float4*>(&v[goff]);
        }
        if (tid < 64) msk[tid] = mask[b * SEQ + kt * 64 + tid];
        __syncthreads();

        // S = Q K^T
        float sc[4][4];
        #pragma unroll
        for (int i = 0; i < 4; i++)
            #pragma unroll
            for (int j = 0; j < 4; j++) sc[i][j] = 0.f;
        #pragma unroll
        for (int d4 = 0; d4 < 16; d4++) {
            float4 qv[4], kv[4];
            #pragma unroll
            for (int i = 0; i < 4; i++)
                qv[i] = *reinterpret_cast<float4*>(&Qs[ty*4+i][d4*4]);
            #pragma unroll
            for (int j = 0; j < 4; j++)
                kv[j] = *reinterpret_cast<float4*>(&Ks[tx*4+j][d4*4]);
            #pragma unroll
            for (int i = 0; i < 4; i++)
                #pragma unroll
                for (int j = 0; j < 4; j++)
                    sc[i][j] += qv[i].x*kv[j].x + qv[i].y*kv[j].y
                              + qv[i].z*kv[j].z + qv[i].w*kv[j].w;
        }

        // scale + causal + padding mask
        const int qb = qt * 64 + ty * 4;
        const int kb = kt * 64 + tx * 4;
        #pragma unroll
        for (int i = 0; i < 4; i++)
            #pragma unroll
            for (int j = 0; j < 4; j++) {
                float val = sc[i][j] * 0.125f;   // 1/sqrt(64)
                bool ok = (kb + j <= qb + i) && (msk[tx*4+j] != 0);
                sc[i][j] = ok ? val : -1e30f;
            }

        // Online softmax; 4 threads-per-row groups of 16 lanes
        #pragma unroll
        for (int i = 0; i < 4; i++) {
            float mx = fmaxf(fmaxf(sc[i][0], sc[i][1]), fmaxf(sc[i][2], sc[i][3]));
            #pragma unroll
            for (int off = 8; off >= 1; off >>= 1)
                mx = fmaxf(mx, __shfl_xor_sync(0xffffffffu, mx, off));
            float nm = fmaxf(mrow[i], mx);
            float alpha = __expf(mrow[i] - nm);
            float rs = 0.f;
            #pragma unroll
            for (int j = 0; j < 4; j++) { sc[i][j] = __expf(sc[i][j] - nm); rs += sc[i][j]; }
            #pragma unroll
            for (int off = 8; off >= 1; off >>= 1)
                rs += __shfl_xor_sync(0xffffffffu, rs, off);
            lrow[i] = lrow[i] * alpha + rs;
            mrow[i] = nm;
            #pragma unroll
            for (int j = 0; j < 4; j++) o[i][j] *= alpha;
            *reinterpret_cast<float4*>(&Ps[ty*4+i][tx*4]) =
                make_float4(sc[i][0], sc[i][1], sc[i][2], sc[i][3]);
        }
        __syncthreads();

        // O += P V
        #pragma unroll 8
        for (int kk = 0; kk < 64; kk++) {
            float4 vv = *reinterpret_cast<float4*>(&Vs[kk][tx*4]);
            #pragma unroll
            for (int i = 0; i < 4; i++) {
                float p = Ps[ty*4+i][kk];
                o[i][0] += p * vv.x; o[i][1] += p * vv.y;
                o[i][2] += p * vv.z; o[i][3] += p * vv.w;
            }
        }
    }

    #pragma unroll
    for (int i = 0; i < 4; i++) {
        float inv = (lrow[i] > 0.f) ? 1.0f / lrow[i] : 0.f;
        float4 out = make_float4(o[i][0]*inv, o[i][1]*inv, o[i][2]*inv, o[i][3]*inv);
        size_t row = (size_t)(b * SEQ + qt * 64 + ty * 4 + i);
        *reinterpret_cast<float4*>(&ctx[row * DM + h * HD + tx * 4]) = out;
    }
}

// ---------------------------------------------------------------------------
extern "C" void kernel_launch(void* const* d_in, const int* in_sizes, int n_in,
                              void* d_out, int out_size)
{
    const float* Q  = (const float*)d_in[0];
    const float* K  = (const float*)d_in[1];
    const float* V  = (const float*)d_in[2];
    const int*   am = (const int*)  d_in[3];
    const float* Wq = (const float*)d_in[4];
    const float* Wk = (const float*)d_in[5];
    const float* Wv = (const float*)d_in[6];
    const float* Wo = (const float*)d_in[7];
    const float* bo = (const float*)d_in[8];
    float* out = (float*)d_out;

    float *q, *k, *v, *ctx;
    cudaGetSymbolAddress((void**)&q,   g_q);
    cudaGetSymbolAddress((void**)&k,   g_k);
    cudaGetSymbolAddress((void**)&v,   g_v);
    cudaGetSymbolAddress((void**)&ctx, g_ctx);

    const dim3 gemm_grid(DM / 128, MROWS / 128);   // (8, 32)
    gemm_nt_kernel<false><<<gemm_grid, 256>>>(Q, Wq, nullptr, q, MROWS, DM, DM);
    gemm_nt_kernel<false><<<gemm_grid, 256>>>(K, Wk, nullptr, k, MROWS, DM, DM);
    gemm_nt_kernel<false><<<gemm_grid, 256>>>(V, Wv, nullptr, v, MROWS, DM, DM);

    const int npairs = MROWS * (DM / 2);
    rope_kernel<<<(npairs + 255) / 256, 256>>>(q, k, npairs);

    const int smem_bytes = (4 * 64 * 68) * (int)sizeof(float) + 64 * (int)sizeof(int);
    cudaFuncSetAttribute(attn_kernel,
                         cudaFuncAttributeMaxDynamicSharedMemorySize, smem_bytes);
    attn_kernel<<<dim3(SEQ / 64, NH, BATCH), 256, smem_bytes>>>(q, k, v, am, ctx);

    gemm_nt_kernel<true><<<gemm_grid, 256>>>(ctx, Wo, bo, out, MROWS, DM, DM);
}